// round 14
// baseline (speedup 1.0000x reference)
#include <cuda_runtime.h>
#include <cuda_fp16.h>
#include <math.h>
#include <stdint.h>

// Problem constants
#define NL 4
#define DM 512
#define NH 8
#define DH 64
#define FFD 2048
#define NB 256
#define NF 30
#define NS 32
#define NROWS (NB*NS)      // 8192
#define NFR   (NB*NF)      // 7680

// GEMM config: CTA tile 128x128, BK=32, 512 threads (16 warps, 4x4),
// warp tile 32x32, 4-stage cp.async pipeline, fp16.
#define SSTAGES 4
#define MATB 8192                 // bytes per matrix per stage (128 rows x 64B)

// ------------------------- scratch (device globals, no allocs) -------------
__device__ __align__(16) float g_x[NROWS*DM];      // residual stream fp32
__device__ __align__(16) float g_proj[NROWS*DM];   // o-proj / ff2 output fp32
__device__ __align__(16) float g_cf[NB*NFR];       // text x frames dots
__device__ __align__(16) float g_cv[NB*NROWS];     // text x video dots

// packed fp16 operand buffers (each unsigned = 2 fp16 along K)
__device__ __align__(16) unsigned g_xh  [NROWS*DM/2];
__device__ __align__(16) unsigned g_qkvh[NROWS*3*DM/2];
__device__ __align__(16) unsigned g_ath [NROWS*DM/2];
__device__ __align__(16) unsigned g_ffh [NROWS*FFD/2];
__device__ __align__(16) unsigned g_wqkvh[NL*3*DM*DM/2];
__device__ __align__(16) unsigned g_woh [NL*DM*DM/2];
__device__ __align__(16) unsigned g_w1h [NL*FFD*DM/2];
__device__ __align__(16) unsigned g_w2h [NL*DM*FFD/2];
__device__ __align__(16) unsigned g_tnh[NB*DM/2],   g_tnl[NB*DM/2];
__device__ __align__(16) unsigned g_fnh[NFR*DM/2];
__device__ __align__(16) unsigned g_vnh[NROWS*DM/2];

// ------------------------- fp16 helpers ------------------------------------
__device__ __forceinline__ void split2h(float f0, float f1, unsigned &h, unsigned &l) {
    __half2 hv = __floats2half2_rn(f0, f1);
    h = reinterpret_cast<unsigned&>(hv);
    float r0 = f0 - __half2float(__low2half(hv));
    float r1 = f1 - __half2float(__high2half(hv));
    __half2 lv = __floats2half2_rn(r0, r1);
    l = reinterpret_cast<unsigned&>(lv);
}

__device__ __forceinline__ unsigned cvt2h(float f0, float f1) {
    __half2 hv = __floats2half2_rn(f0, f1);
    return reinterpret_cast<unsigned&>(hv);
}

__device__ __forceinline__ float2 h2f(unsigned u) {
    __half2 h = reinterpret_cast<__half2&>(u);
    return __half22float2(h);
}

__device__ __forceinline__ uint32_t smem_u32(const void* p) {
    uint32_t a;
    asm("{ .reg .u64 t; cvta.to.shared.u64 t, %1; cvt.u32.u64 %0, t; }"
        : "=r"(a) : "l"(p));
    return a;
}

#define MMA_F16(d, a, b0, b1) \
    asm volatile("mma.sync.aligned.m16n8k16.row.col.f32.f16.f16.f32 " \
                 "{%0,%1,%2,%3}, {%4,%5,%6,%7}, {%8,%9}, {%0,%1,%2,%3};" \
                 : "+f"(d[0]), "+f"(d[1]), "+f"(d[2]), "+f"(d[3]) \
                 : "r"(a[0]), "r"(a[1]), "r"(a[2]), "r"(a[3]), \
                   "r"(b0), "r"(b1))

#define LDSM4(r, addr) \
    asm volatile("ldmatrix.sync.aligned.m8n8.x4.shared.b16 {%0,%1,%2,%3}, [%4];" \
                 : "=r"((r)[0]), "=r"((r)[1]), "=r"((r)[2]), "=r"((r)[3]) \
                 : "r"(addr))

#define CP_ASYNC16(dst, src) \
    asm volatile("cp.async.cg.shared.global [%0], [%1], 16;" \
                 :: "r"(dst), "l"(src) : "memory")

#define CP_COMMIT() asm volatile("cp.async.commit_group;" ::: "memory")
#define CP_WAIT2()  asm volatile("cp.async.wait_group 2;" ::: "memory")

// ------------------------- fp16 mma.sync GEMM ------------------------------
// C[M,N] = A[M,K]*B[N,K]^T (+bias)(relu). B single fp16.
// USE_LO=false: A single fp16 (1 MMA/tile). USE_LO=true: A hi/lo (2 MMA/tile).
template<bool USE_LO>
__global__ __launch_bounds__(512) void mma_gemm(
    const unsigned* __restrict__ Ah, const unsigned* __restrict__ Al,
    const unsigned* __restrict__ Bh,
    const float* __restrict__ bias, float* __restrict__ C,
    unsigned* __restrict__ Ch,
    int M, int N, int K, int relu)
{
    constexpr int NMAT = USE_LO ? 3 : 2;
    constexpr int STAGEB = NMAT * MATB;

    extern __shared__ __align__(16) char dsm[];
    const uint32_t sbase = smem_u32(dsm);

    const int tid  = threadIdx.x;
    const int warp = tid >> 5;
    const int lane = tid & 31;
    const int g = lane >> 2;        // 0..7
    const int t = lane & 3;         // 0..3
    const int wm = (warp & 3) * 32;
    const int wn = (warp >> 2) * 32;
    const int bm = blockIdx.y * 128;
    const int bn = blockIdx.x * 128;

    // ---- cp.async mapping: each thread loads one 16B chunk per matrix -----
    const int lrow = tid >> 2;      // 0..127
    const int lc   = tid & 3;       // 16B chunk within 64B row
    const int Kc16 = K >> 3;        // 16B chunks per global row
    const uint32_t swoff = lrow * 64 + ((lc ^ ((lrow >> 1) & 3)) << 4);

    const char* gAh = (const char*)Ah + ((size_t)(bm + lrow) * Kc16 + lc) * 16;
    const char* gAl = USE_LO ? (const char*)Al + ((size_t)(bm + lrow) * Kc16 + lc) * 16 : nullptr;
    const char* gBh = (const char*)Bh + ((size_t)(bn + lrow) * Kc16 + lc) * 16;

    auto load_stage = [&](int chunk, int stage) {
        const size_t go = (size_t)chunk * 64;
        const uint32_t d = sbase + stage * STAGEB + swoff;
        CP_ASYNC16(d, gAh + go);
        if (USE_LO) CP_ASYNC16(d + MATB, gAl + go);
        CP_ASYNC16(d + (NMAT - 1) * MATB, gBh + go);
    };

    // ---- ldmatrix base addresses (stage 0, k-step 0) ----------------------
    const int mat  = lane >> 3;     // 0..3
    const int mrow = lane & 7;      // 0..7
    uint32_t aB[2][2], bB[2];       // [term][mt] / [pair]
#pragma unroll
    for (int mt = 0; mt < 2; mt++) {
        const int r = wm + mt * 16 + (mat & 1) * 8 + mrow;
        const uint32_t off = r * 64 + ((((unsigned)mat >> 1) ^ ((r >> 1) & 3)) << 4);
        aB[0][mt] = sbase + off;                       // Ah
        if (USE_LO) aB[1][mt] = sbase + MATB + off;    // Al
    }
#pragma unroll
    for (int p = 0; p < 2; p++) {
        const int r = wn + p * 16 + (mat >> 1) * 8 + mrow;
        const uint32_t off = r * 64 + ((((unsigned)mat & 1) ^ ((r >> 1) & 3)) << 4);
        bB[p] = sbase + (NMAT - 1) * MATB + off;       // Bh
    }

    float acc[2][4][4];
#pragma unroll
    for (int mt = 0; mt < 2; mt++)
#pragma unroll
        for (int nt = 0; nt < 4; nt++)
#pragma unroll
            for (int i = 0; i < 4; i++) acc[mt][nt][i] = 0.f;

    auto compute = [&](int stage) {
        const uint32_t so = stage * STAGEB;
#pragma unroll
        for (int s = 0; s < 2; s++) {
            const uint32_t sx = (uint32_t)(s << 5);   // k-step toggles bit5
            unsigned ah[2][4], al[2][4], bh[2][4];
#pragma unroll
            for (int mt = 0; mt < 2; mt++) {
                LDSM4(ah[mt], (aB[0][mt] + so) ^ sx);
                if (USE_LO) LDSM4(al[mt], (aB[1][mt] + so) ^ sx);
            }
#pragma unroll
            for (int p = 0; p < 2; p++) {
                LDSM4(bh[p], (bB[p] + so) ^ sx);
            }
#pragma unroll
            for (int mt = 0; mt < 2; mt++)
#pragma unroll
                for (int nt = 0; nt < 4; nt++) {
                    const int p = nt >> 1, u = (nt & 1) * 2;
                    MMA_F16(acc[mt][nt], ah[mt], bh[p][u], bh[p][u+1]);
                    if (USE_LO)
                        MMA_F16(acc[mt][nt], al[mt], bh[p][u], bh[p][u+1]);
                }
        }
    };

    const int NC = K >> 5;          // K/32 chunks

    load_stage(0, 0); CP_COMMIT();
    load_stage(1, 1); CP_COMMIT();
    load_stage(2, 2); CP_COMMIT();

    for (int c = 0; c < NC; c++) {
        CP_WAIT2();
        __syncthreads();
        if (c + 3 < NC) load_stage(c + 3, (c + 3) & 3);
        CP_COMMIT();
        compute(c & 3);
    }

    // ---- epilogue ---------------------------------------------------------
#pragma unroll
    for (int mt = 0; mt < 2; mt++) {
        const int r0 = bm + wm + mt * 16 + g;
#pragma unroll
        for (int nt = 0; nt < 4; nt++) {
            const int c = bn + wn + nt * 8 + 2 * t;
            float b0 = 0.f, b1 = 0.f;
            if (bias) { b0 = __ldg(bias + c); b1 = __ldg(bias + c + 1); }
            float v00 = acc[mt][nt][0] + b0;
            float v01 = acc[mt][nt][1] + b1;
            float v10 = acc[mt][nt][2] + b0;
            float v11 = acc[mt][nt][3] + b1;
            if (relu) {
                v00 = fmaxf(v00, 0.f); v01 = fmaxf(v01, 0.f);
                v10 = fmaxf(v10, 0.f); v11 = fmaxf(v11, 0.f);
            }
            if (Ch) {
                Ch[((size_t)r0 * N + c) >> 1]       = cvt2h(v00, v01);
                Ch[((size_t)(r0 + 8) * N + c) >> 1] = cvt2h(v10, v11);
            } else {
                *reinterpret_cast<float2*>(C + (size_t)r0 * N + c) = make_float2(v00, v01);
                *reinterpret_cast<float2*>(C + (size_t)(r0 + 8) * N + c) = make_float2(v10, v11);
            }
        }
    }
}

// ------------------------- merged weight conversion ------------------------
// Converts 4 weight regions fp32 -> fp16 pairs, one launch, float4 per thread.
__global__ void cvt_weights(const float* __restrict__ s0, unsigned* __restrict__ d0, int n0,
                            const float* __restrict__ s1, unsigned* __restrict__ d1, int n1,
                            const float* __restrict__ s2, unsigned* __restrict__ d2, int n2,
                            const float* __restrict__ s3, unsigned* __restrict__ d3, int n3) {
    int i = blockIdx.x * 256 + threadIdx.x;   // pair-of-words index (4 floats)
    int lw = i * 2;                            // word offset in concatenated space
    const float* s; unsigned* d;
    if (lw < n0) { s = s0; d = d0; }
    else { lw -= n0;
        if (lw < n1) { s = s1; d = d1; }
        else { lw -= n1;
            if (lw < n2) { s = s2; d = d2; }
            else { lw -= n2; if (lw >= n3) return; s = s3; d = d3; }
        }
    }
    float4 v = *reinterpret_cast<const float4*>(s + (size_t)lw * 2);
    d[lw]     = cvt2h(v.x, v.y);
    d[lw + 1] = cvt2h(v.z, v.w);
}

// ------------------------- build x = [frames; expansion] (+cvt) ------------
__global__ void build_x_split(const float* __restrict__ fr,
                              const float* __restrict__ ex,
                              float* __restrict__ x,
                              unsigned* __restrict__ xh) {
    int i = blockIdx.x * 256 + threadIdx.x;   // over NROWS*128 float4 units
    int c4 = i & 127;
    int row = i >> 7;
    int b = row >> 5;
    int s = row & 31;
    float4 v = (s < NF)
        ? *reinterpret_cast<const float4*>(fr + ((size_t)(b * NF + s) * DM + c4 * 4))
        : *reinterpret_cast<const float4*>(ex + ((size_t)(s - NF) * DM + c4 * 4));
    *reinterpret_cast<float4*>(x + (size_t)row * DM + c4 * 4) = v;
    uint2 u = make_uint2(cvt2h(v.x, v.y), cvt2h(v.z, v.w));
    *reinterpret_cast<uint2*>(xh + (size_t)row * 256 + c4 * 2) = u;
}

// ------------------------- attention (fp16 qkv in, fp16 out) ---------------
__global__ __launch_bounds__(1024) void attn_h(const unsigned* __restrict__ qkvh,
                                               unsigned* __restrict__ oh) {
    const int b = blockIdx.x;
    const int hh = blockIdx.y;
    __shared__ float sq[32][65];
    __shared__ float sk[32][65];
    __shared__ float sv[32][65];
    __shared__ float sp[32][33];
    const int tx = threadIdx.x;   // 0..31
    const int ty = threadIdx.y;   // 0..31

    const size_t wbase = (size_t)(b * NS + ty) * 768 + hh * 32 + tx;
    float2 q2 = h2f(qkvh[wbase]);
    float2 k2 = h2f(qkvh[wbase + 256]);
    float2 v2 = h2f(qkvh[wbase + 512]);
    sq[ty][2 * tx] = q2.x; sq[ty][2 * tx + 1] = q2.y;
    sk[ty][2 * tx] = k2.x; sk[ty][2 * tx + 1] = k2.y;
    sv[ty][2 * tx] = v2.x; sv[ty][2 * tx + 1] = v2.y;
    __syncthreads();

    float acc = 0.f;
#pragma unroll
    for (int d = 0; d < DH; d++) acc += sq[ty][d] * sk[tx][d];
    acc *= 0.125f; // 1/sqrt(64)

    float m = acc;
#pragma unroll
    for (int o = 16; o; o >>= 1) m = fmaxf(m, __shfl_xor_sync(0xffffffffu, m, o));
    float e = __expf(acc - m);
    float s = e;
#pragma unroll
    for (int o = 16; o; o >>= 1) s += __shfl_xor_sync(0xffffffffu, s, o);
    sp[ty][tx] = e / s;
    __syncthreads();

    float o0 = 0.f, o1 = 0.f;
#pragma unroll
    for (int k = 0; k < NS; k++) {
        float p = sp[ty][k];
        o0 += p * sv[k][2 * tx];
        o1 += p * sv[k][2 * tx + 1];
    }
    oh[(size_t)(b * NS + ty) * 256 + hh * 32 + tx] = cvt2h(o0, o1);
}

// ------------------------- warp-per-row LayerNorm (+cvt) -------------------
// x = LayerNorm(x + o)*g + b, writes fp32 x and fp16 xh. 32 rows per block.
__global__ __launch_bounds__(1024) void add_ln_warp(float* __restrict__ x,
                                                    const float* __restrict__ o,
                                                    const float* __restrict__ g,
                                                    const float* __restrict__ bt,
                                                    unsigned* __restrict__ xh) {
    const int w = threadIdx.x >> 5;
    const int lane = threadIdx.x & 31;
    const int row = blockIdx.x * 32 + w;
    float* xr = x + (size_t)row * DM;
    const float* orr = o + (size_t)row * DM;

    float4 v[4];
    float s = 0.f, s2 = 0.f;
#pragma unroll
    for (int i = 0; i < 4; i++) {
        const int e = (lane + 32 * i) * 4;
        float4 a = *reinterpret_cast<const float4*>(xr + e);
        float4 b = *reinterpret_cast<const float4*>(orr + e);
        a.x += b.x; a.y += b.y; a.z += b.z; a.w += b.w;
        v[i] = a;
        s  += a.x + a.y + a.z + a.w;
        s2 += a.x * a.x + a.y * a.y + a.z * a.z + a.w * a.w;
    }
#pragma unroll
    for (int off = 16; off; off >>= 1) {
        s  += __shfl_xor_sync(0xffffffffu, s, off);
        s2 += __shfl_xor_sync(0xffffffffu, s2, off);
    }
    const float mean = s * (1.f / DM);
    const float var = fmaxf(s2 * (1.f / DM) - mean * mean, 0.f);
    const float rs = rsqrtf(var + 1e-5f);

#pragma unroll
    for (int i = 0; i < 4; i++) {
        const int e = (lane + 32 * i) * 4;
        float4 gg = *reinterpret_cast<const float4*>(g + e);
        float4 bb = *reinterpret_cast<const float4*>(bt + e);
        float4 r;
        r.x = (v[i].x - mean) * rs * gg.x + bb.x;
        r.y = (v[i].y - mean) * rs * gg.y + bb.y;
        r.z = (v[i].z - mean) * rs * gg.z + bb.z;
        r.w = (v[i].w - mean) * rs * gg.w + bb.w;
        *reinterpret_cast<float4*>(xr + e) = r;
        uint2 u = make_uint2(cvt2h(r.x, r.y), cvt2h(r.z, r.w));
        *reinterpret_cast<uint2*>(xh + (size_t)row * 256 + e / 2) = u;
    }
}

// ------------------------- warp-per-row l2 normalize (+cvt/split) ----------
__global__ __launch_bounds__(1024) void l2norm_warp(const float* __restrict__ in,
                                                    unsigned* __restrict__ oh,
                                                    unsigned* __restrict__ ol) {
    const int w = threadIdx.x >> 5;
    const int lane = threadIdx.x & 31;
    const int row = blockIdx.x * 32 + w;
    const float* r = in + (size_t)row * DM;

    float4 v[4];
    float ss = 0.f;
#pragma unroll
    for (int i = 0; i < 4; i++) {
        v[i] = *reinterpret_cast<const float4*>(r + (lane + 32 * i) * 4);
        ss += v[i].x * v[i].x + v[i].y * v[i].y + v[i].z * v[i].z + v[i].w * v[i].w;
    }
#pragma unroll
    for (int off = 16; off; off >>= 1)
        ss += __shfl_xor_sync(0xffffffffu, ss, off);
    const float inv = 1.f / fmaxf(sqrtf(ss), 1e-12f);

#pragma unroll
    for (int i = 0; i < 4; i++) {
        const int e = (lane + 32 * i) * 4;
        float f0 = v[i].x * inv, f1 = v[i].y * inv;
        float f2 = v[i].z * inv, f3 = v[i].w * inv;
        if (ol) {
            unsigned h0, l0, h1, l1;
            split2h(f0, f1, h0, l0);
            split2h(f2, f3, h1, l1);
            *reinterpret_cast<uint2*>(oh + (size_t)row * 256 + e / 2) = make_uint2(h0, h1);
            *reinterpret_cast<uint2*>(ol + (size_t)row * 256 + e / 2) = make_uint2(l0, l1);
        } else {
            uint2 u = make_uint2(cvt2h(f0, f1), cvt2h(f2, f3));
            *reinterpret_cast<uint2*>(oh + (size_t)row * 256 + e / 2) = u;
        }
    }
}

// ------------------------- MaxSim reduce + output --------------------------
__global__ void sim_out_kernel(const float* __restrict__ cf,
                               const float* __restrict__ cv,
                               float* __restrict__ out) {
    int p = blockIdx.x * 256 + threadIdx.x;  // 65536 pairs
    int i = p >> 8;
    int j = p & 255;
    const float* pf = cf + (size_t)i * NFR + j * NF;
    float mf = -1e30f;
#pragma unroll
    for (int f = 0; f < NF; f++) mf = fmaxf(mf, pf[f]);
    const float* pv = cv + (size_t)i * NROWS + j * NS;
    float mv = -1e30f;
#pragma unroll
    for (int v = 0; v < NS; v++) mv = fmaxf(mv, pv[v]);
    out[p]               = mf + mv;
    out[NB * NB + p]     = mf;
    out[2 * NB * NB + p] = mv;
}

// ------------------------- launcher ----------------------------------------
#define SMEM1 (SSTAGES * 2 * MATB)   // 65536 (USE_LO=false)
#define SMEM2 (SSTAGES * 3 * MATB)   // 98304 (USE_LO=true)

extern "C" void kernel_launch(void* const* d_in, const int* in_sizes, int n_in,
                              void* d_out, int out_size) {
    const float* text  = (const float*)d_in[0];
    const float* fr    = (const float*)d_in[1];
    const float* ex    = (const float*)d_in[2];
    const float* Wqkv  = (const float*)d_in[3];
    const float* bqkv  = (const float*)d_in[4];
    const float* Wo    = (const float*)d_in[5];
    const float* bo    = (const float*)d_in[6];
    const float* ln1w  = (const float*)d_in[7];
    const float* ln1b  = (const float*)d_in[8];
    const float* W1    = (const float*)d_in[9];
    const float* b1    = (const float*)d_in[10];
    const float* W2    = (const float*)d_in[11];
    const float* b2    = (const float*)d_in[12];
    const float* ln2w  = (const float*)d_in[13];
    const float* ln2b  = (const float*)d_in[14];
    float* out = (float*)d_out;

    float *px, *pproj, *pcf, *pcv;
    unsigned *pxh, *pqkvh, *path, *pffh;
    unsigned *pwqkvh, *pwoh, *pw1h, *pw2h;
    unsigned *ptnh, *ptnl, *pfnh, *pvnh;
    cudaGetSymbolAddress((void**)&px,     g_x);
    cudaGetSymbolAddress((void**)&pproj,  g_proj);
    cudaGetSymbolAddress((void**)&pcf,    g_cf);
    cudaGetSymbolAddress((void**)&pcv,    g_cv);
    cudaGetSymbolAddress((void**)&pxh,    g_xh);
    cudaGetSymbolAddress((void**)&pqkvh,  g_qkvh);
    cudaGetSymbolAddress((void**)&path,   g_ath);
    cudaGetSymbolAddress((void**)&pffh,   g_ffh);
    cudaGetSymbolAddress((void**)&pwqkvh, g_wqkvh);
    cudaGetSymbolAddress((void**)&pwoh,   g_woh);
    cudaGetSymbolAddress((void**)&pw1h,   g_w1h);
    cudaGetSymbolAddress((void**)&pw2h,   g_w2h);
    cudaGetSymbolAddress((void**)&ptnh,   g_tnh);
    cudaGetSymbolAddress((void**)&ptnl,   g_tnl);
    cudaGetSymbolAddress((void**)&pfnh,   g_fnh);
    cudaGetSymbolAddress((void**)&pvnh,   g_vnh);

    cudaFuncSetAttribute(mma_gemm<false>, cudaFuncAttributeMaxDynamicSharedMemorySize, SMEM1);
    cudaFuncSetAttribute(mma_gemm<true>,  cudaFuncAttributeMaxDynamicSharedMemorySize, SMEM2);

    // merged weight conversion (one launch)
    {
        const int n0 = NL * 3 * DM * DM / 2;
        const int n1 = NL * DM * DM / 2;
        const int n2 = NL * FFD * DM / 2;
        const int n3 = NL * DM * FFD / 2;
        const int pairs = (n0 + n1 + n2 + n3) / 2;
        cvt_weights<<<(pairs + 255) / 256, 256>>>(
            Wqkv, pwqkvh, n0, Wo, pwoh, n1, W1, pw1h, n2, W2, pw2h, n3);
    }

    build_x_split<<<(NROWS * DM / 4) / 256, 256>>>(fr, ex, px, pxh);

    for (int l = 0; l < NL; l++) {
        // QKV: [8192,512] x [1536,512]^T -> fp16 directly
        mma_gemm<false><<<dim3(3 * DM / 128, NROWS / 128), 512, SMEM1>>>(
            pxh, nullptr, pwqkvh + (size_t)l * 3 * DM * DM / 2,
            bqkv + (size_t)l * 3 * DM, nullptr, pqkvh,
            NROWS, 3 * DM, DM, 0);
        // attention per (batch, head), fp16 in/out
        attn_h<<<dim3(NB, NH), dim3(32, 32)>>>(pqkvh, path);
        // O projection -> fp32
        mma_gemm<false><<<dim3(DM / 128, NROWS / 128), 512, SMEM1>>>(
            path, nullptr, pwoh + (size_t)l * DM * DM / 2,
            bo + (size_t)l * DM, pproj, nullptr,
            NROWS, DM, DM, 0);
        add_ln_warp<<<NROWS / 32, 1024>>>(px, pproj, ln1w + (size_t)l * DM,
                                          ln1b + (size_t)l * DM, pxh);
        // FF1 (+ReLU), writes fp16 output directly
        mma_gemm<false><<<dim3(FFD / 128, NROWS / 128), 512, SMEM1>>>(
            pxh, nullptr, pw1h + (size_t)l * FFD * DM / 2,
            b1 + (size_t)l * FFD, nullptr, pffh,
            NROWS, FFD, DM, 1);
        // FF2 -> fp32
        mma_gemm<false><<<dim3(DM / 128, NROWS / 128), 512, SMEM1>>>(
            pffh, nullptr, pw2h + (size_t)l * DM * FFD / 2,
            b2 + (size_t)l * DM, pproj, nullptr,
            NROWS, DM, FFD, 0);
        add_ln_warp<<<NROWS / 32, 1024>>>(px, pproj, ln2w + (size_t)l * DM,
                                          ln2b + (size_t)l * DM, pxh);
    }

    // normalizations (text keeps hi/lo for MaxSim precision)
    l2norm_warp<<<NB / 32, 1024>>>(text, ptnh, ptnl);
    l2norm_warp<<<NFR / 32, 1024>>>(fr, pfnh, nullptr);
    l2norm_warp<<<NROWS / 32, 1024>>>(px, pvnh, nullptr);

    // similarity dot-product GEMMs -> fp32 (text hi/lo, 2-MMA path)
    mma_gemm<true><<<dim3(NFR / 128, NB / 128), 512, SMEM2>>>(
        ptnh, ptnl, pfnh, nullptr, pcf, nullptr, NB, NFR, DM, 0);
    mma_gemm<true><<<dim3(NROWS / 128, NB / 128), 512, SMEM2>>>(
        ptnh, ptnl, pvnh, nullptr, pcv, nullptr, NB, NROWS, DM, 0);

    // MaxSim + write three output matrices
    sim_out_kernel<<<(NB * NB) / 256, 256>>>(pcf, pcv, out);
}